// round 14
// baseline (speedup 1.0000x reference)
#include <cuda_runtime.h>
#include <cuda_bf16.h>
#include <math.h>

// B=16384 samples, L=256 latents, H=16 hidden.
// out[b,l] = sigmoid( sum_h W2[l,h]*softplus(y[b,l]*W1[l,h]+b1[l,h]) + b2[l] )
//
// Single fused kernel, 148 CTAs x 512 threads (1 CTA/SM, 128 regs/thread):
//  CTAs 0..16: build grid point bid (2 threads/latent, 8 h-terms each,
//    shfl reduce), publish to g_pts, bump g_built.
//  All threads: issue ALL 14 y loads up front (clamped), then poll g_built,
//  assemble cubic coefficients into swizzled smem, and retire 14x4
//  interp+store with fully independent LDS/FMA chains.

#define LATENTS 256
#define HID     16
#define NINT    16
#define NPTS    (NINT + 1)
#define Y_LO    (-6.5f)
#define STEP_F  (13.0f / (float)NINT)
#define INVH_F  ((float)NINT / 13.0f)
#define OFF_F   8.0f                       // -Y_LO * INVH

#define EV_GRID  148
#define EV_BLK   512
#define DEPTH    14                        // ceil(1048576 / (148*512))
#define TAB_F4   (NINT * LATENTS)          // 4096 float4 = 65536 B

// Global scratch (allocation-free). Counters are monotonic => replay-safe.
__device__ float2 g_pts[NPTS * LATENTS];
__device__ unsigned long long g_ticket = 0;  // +148 per launch
__device__ unsigned long long g_built  = 0;  // +17  per launch

__device__ __forceinline__ float interp1(float yv, const float4* __restrict__ col)
{
    float t = fmaf(yv, INVH_F, OFF_F);
    t = fminf(fmaxf(t, 0.0f), (float)NINT - 5e-4f);
    const int   i = (int)t;
    const float u = t - (float)i;
    const float4 c = col[i * LATENTS];     // stride 4096B per interval
    return fmaf(fmaf(fmaf(c.w, u, c.z), u, c.y), u, c.x);
}

__global__ __launch_bounds__(EV_BLK, 1)
void fused_kernel(const float4* __restrict__ y4,
                  float4* __restrict__ out4,
                  const float* __restrict__ W1,
                  const float* __restrict__ b1,
                  const float* __restrict__ W2,
                  const float* __restrict__ b2,
                  int n4)
{
    extern __shared__ float4 tab[];        // [NINT][256] swizzled

    const int gtid = blockIdx.x * EV_BLK + threadIdx.x;
    const int S    = EV_GRID * EV_BLK;     // 75776 float4s; multiple of 64

    // ---- producers first: CTAs 0..16 build grid point = blockIdx.x ----
    // 2 threads per latent, 8 h-terms each, reduce via one shfl_xor.
    if (blockIdx.x < NPTS) {
        const int l = threadIdx.x >> 1;            // 0..255
        const int q = threadIdx.x & 1;             // h-half
        const float y0 = Y_LO + STEP_F * (float)blockIdx.x;

        float a  = (q == 0) ? b2[l] : 0.0f;
        float da = 0.0f;
#pragma unroll
        for (int k = 0; k < 8; ++k) {
            const int h = q * 8 + k;
            const float w1 = W1[l * HID + h];
            const float bb = b1[l * HID + h];
            const float w2 = W2[l * HID + h];
            const float x  = fmaf(y0, w1, bb);
            const float e  = __expf(-fabsf(x));                 // <= 1
            const float iv = __fdividef(1.0f, 1.0f + e);
            const float sp = fmaxf(x, 0.0f) + __logf(1.0f + e); // softplus
            const float s  = (x >= 0.0f) ? iv : e * iv;         // sigmoid
            a  = fmaf(w2, sp, a);
            da = fmaf(w2 * s, w1, da);
        }
        a  += __shfl_xor_sync(0xffffffffu, a, 1);
        da += __shfl_xor_sync(0xffffffffu, da, 1);
        if (q == 0) {
            const float eo = __expf(-a);
            const float g  = __fdividef(1.0f, 1.0f + eo);
            g_pts[blockIdx.x * LATENTS + l] =
                make_float2(g, STEP_F * (g * (1.0f - g) * da));
        }
        __syncthreads();
        if (threadIdx.x == 0) {
            __threadfence();               // release g_pts writes
            atomicAdd(&g_built, 1ULL);
        }
    }

    // ---- issue the ENTIRE per-thread load set (clamped, branch-free) ----
    float4 v[DEPTH];
#pragma unroll
    for (int k = 0; k < DEPTH; ++k) {
        int id = gtid + k * S;
        id = (id < n4) ? id : (n4 - 1);    // clamp: duplicate load, masked store
        v[k] = y4[id];
    }

    // ---- wait until all 17 producers of THIS launch have published ----
    if (threadIdx.x == 0) {
        const unsigned long long ticket = atomicAdd(&g_ticket, 1ULL);
        const unsigned long long target =
            (ticket / (unsigned long long)EV_GRID + 1ULL) * (unsigned long long)NPTS;
        while (*((volatile unsigned long long*)&g_built) < target)
            __nanosleep(32);
    }
    __syncthreads();
    __threadfence();                       // acquire: g_pts reads after spin

    // ---- assemble coefficients into swizzled smem (8 iters/thread) ----
#pragma unroll
    for (int t = threadIdx.x; t < TAB_F4; t += EV_BLK) {
        const int ivp = t >> 8;                    // 0..15
        const int lp  = t & (LATENTS - 1);
        const float2 p0 = g_pts[ivp * LATENTS + lp];
        const float2 p1 = g_pts[(ivp + 1) * LATENTS + lp];
        float4 c;
        c.x = p0.x;
        c.y = p0.y;
        c.z = 3.0f * (p1.x - p0.x) - 2.0f * p0.y - p1.y;
        c.w = 2.0f * (p0.x - p1.x) + p0.y + p1.y;
        tab[ivp * LATENTS + (lp & 3) * 64 + (lp >> 2)] = c;
    }
    __syncthreads();

    // ---- retire all 14 batches: 56 independent interp chains ----
    // Thread handles latents l = 4*lg+j (lg = gtid & 63); per-j LDS.128 is
    // stride-16B across lanes (conflict-free); iv adds multiples of 4096B.
    const int lg = gtid & 63;
    const float4* c0 = tab + lg;
    const float4* c1 = tab + lg + 64;
    const float4* c2 = tab + lg + 128;
    const float4* c3 = tab + lg + 192;

#pragma unroll
    for (int k = 0; k < DEPTH; ++k) {
        float4 r;
        r.x = interp1(v[k].x, c0);
        r.y = interp1(v[k].y, c1);
        r.z = interp1(v[k].z, c2);
        r.w = interp1(v[k].w, c3);
        const int id = gtid + k * S;
        if (id < n4) out4[id] = r;
    }
}

extern "C" void kernel_launch(void* const* d_in, const int* in_sizes, int n_in,
                              void* d_out, int out_size)
{
    // metadata order: t, y, W1, b1, W2, b2, args
    const float* y  = (const float*)d_in[1];
    const float* W1 = (const float*)d_in[2];
    const float* b1 = (const float*)d_in[3];
    const float* W2 = (const float*)d_in[4];
    const float* b2 = (const float*)d_in[5];
    float* out = (float*)d_out;

    const int total = in_sizes[1];         // B*L = 4,194,304 (multiple of 4)
    const int n4 = total / 4;

    static int smem_set = 0;
    const int smem_bytes = TAB_F4 * (int)sizeof(float4);   // 65536
    if (!smem_set) {
        cudaFuncSetAttribute(fused_kernel,
                             cudaFuncAttributeMaxDynamicSharedMemorySize,
                             smem_bytes);
        smem_set = 1;
    }

    fused_kernel<<<EV_GRID, EV_BLK, smem_bytes>>>(
        (const float4*)y, (float4*)out, W1, b1, W2, b2, n4);
}

// round 16
// speedup vs baseline: 1.3266x; 1.3266x over previous
#include <cuda_runtime.h>
#include <cuda_bf16.h>
#include <math.h>

// B=16384 samples, L=256 latents, H=16 hidden.
// out[b,l] = sigmoid( sum_h W2[l,h]*softplus(y[b,l]*W1[l,h]+b1[l,h]) + b2[l] )
//
// Single fused kernel, 148 CTAs x 1024 threads (1 CTA/SM, 64 regs/thread):
//  CTAs 0..16: build grid point bid (4 threads/latent, 4 h-terms each,
//    shfl reduce), publish to g_pts, bump g_built.
//  All threads: issue ALL 7 y loads up front (clamped), poll g_built,
//  assemble cubic coefficients into swizzled smem, retire 7x4 interp+store.

#define LATENTS 256
#define HID     16
#define NINT    16
#define NPTS    (NINT + 1)
#define Y_LO    (-6.5f)
#define STEP_F  (13.0f / (float)NINT)
#define INVH_F  ((float)NINT / 13.0f)
#define OFF_F   8.0f                       // -Y_LO * INVH

#define EV_GRID  148
#define EV_BLK   1024
#define DEPTH    7                         // 148*1024*7 = 1060864 >= n4
#define TAB_F4   (NINT * LATENTS)          // 4096 float4 = 65536 B

// Global scratch (allocation-free). Counters are monotonic => replay-safe.
__device__ float2 g_pts[NPTS * LATENTS];
__device__ unsigned long long g_ticket = 0;  // +148 per launch
__device__ unsigned long long g_built  = 0;  // +17  per launch

__device__ __forceinline__ float interp1(float yv, const float4* __restrict__ col)
{
    float t = fmaf(yv, INVH_F, OFF_F);
    t = fminf(fmaxf(t, 0.0f), (float)NINT - 5e-4f);
    const int   i = (int)t;
    const float u = t - (float)i;
    const float4 c = col[i * LATENTS];     // stride 4096B per interval
    return fmaf(fmaf(fmaf(c.w, u, c.z), u, c.y), u, c.x);
}

__global__ __launch_bounds__(EV_BLK, 1)
void fused_kernel(const float4* __restrict__ y4,
                  float4* __restrict__ out4,
                  const float* __restrict__ W1,
                  const float* __restrict__ b1,
                  const float* __restrict__ W2,
                  const float* __restrict__ b2,
                  int n4)
{
    extern __shared__ float4 tab[];        // [NINT][256] swizzled

    const int gtid = blockIdx.x * EV_BLK + threadIdx.x;
    const int S    = EV_GRID * EV_BLK;     // 151552 float4s; multiple of 64

    // ---- producers first: CTAs 0..16 build grid point = blockIdx.x ----
    // 4 threads per latent, 4 h-terms each, reduce via shfl_xor (lanes 1,2).
    if (blockIdx.x < NPTS) {
        const int l = threadIdx.x >> 2;            // 0..255
        const int q = threadIdx.x & 3;             // h-quarter
        const float y0 = Y_LO + STEP_F * (float)blockIdx.x;

        float a  = (q == 0) ? b2[l] : 0.0f;
        float da = 0.0f;
#pragma unroll
        for (int k = 0; k < 4; ++k) {
            const int h = q * 4 + k;
            const float w1 = W1[l * HID + h];
            const float bb = b1[l * HID + h];
            const float w2 = W2[l * HID + h];
            const float x  = fmaf(y0, w1, bb);
            const float e  = __expf(-fabsf(x));                 // <= 1
            const float iv = __fdividef(1.0f, 1.0f + e);
            const float sp = fmaxf(x, 0.0f) + __logf(1.0f + e); // softplus
            const float s  = (x >= 0.0f) ? iv : e * iv;         // sigmoid
            a  = fmaf(w2, sp, a);
            da = fmaf(w2 * s, w1, da);
        }
        a  += __shfl_xor_sync(0xffffffffu, a, 1);
        da += __shfl_xor_sync(0xffffffffu, da, 1);
        a  += __shfl_xor_sync(0xffffffffu, a, 2);
        da += __shfl_xor_sync(0xffffffffu, da, 2);
        if (q == 0) {
            const float eo = __expf(-a);
            const float g  = __fdividef(1.0f, 1.0f + eo);
            g_pts[blockIdx.x * LATENTS + l] =
                make_float2(g, STEP_F * (g * (1.0f - g) * da));
        }
        __syncthreads();
        if (threadIdx.x == 0) {
            __threadfence();               // release g_pts writes
            atomicAdd(&g_built, 1ULL);
        }
    }

    // ---- issue the ENTIRE per-thread load set (clamped, branch-free) ----
    float4 v[DEPTH];
#pragma unroll
    for (int k = 0; k < DEPTH; ++k) {
        int id = gtid + k * S;
        id = (id < n4) ? id : (n4 - 1);    // clamp: duplicate load, masked store
        v[k] = y4[id];
    }

    // ---- wait until all 17 producers of THIS launch have published ----
    if (threadIdx.x == 0) {
        const unsigned long long ticket = atomicAdd(&g_ticket, 1ULL);
        const unsigned long long target =
            (ticket / (unsigned long long)EV_GRID + 1ULL) * (unsigned long long)NPTS;
        while (*((volatile unsigned long long*)&g_built) < target)
            __nanosleep(32);
    }
    __syncthreads();
    __threadfence();                       // acquire: g_pts reads after spin

    // ---- assemble coefficients into swizzled smem (4 iters/thread) ----
#pragma unroll
    for (int t = threadIdx.x; t < TAB_F4; t += EV_BLK) {
        const int ivp = t >> 8;                    // 0..15
        const int lp  = t & (LATENTS - 1);
        const float2 p0 = g_pts[ivp * LATENTS + lp];
        const float2 p1 = g_pts[(ivp + 1) * LATENTS + lp];
        float4 c;
        c.x = p0.x;
        c.y = p0.y;
        c.z = 3.0f * (p1.x - p0.x) - 2.0f * p0.y - p1.y;
        c.w = 2.0f * (p0.x - p1.x) + p0.y + p1.y;
        tab[ivp * LATENTS + (lp & 3) * 64 + (lp >> 2)] = c;
    }
    __syncthreads();

    // ---- retire all 7 batches: 28 independent interp chains ----
    // Thread handles latents l = 4*lg+j (lg = gtid & 63); per-j LDS.128 is
    // stride-16B across lanes (conflict-free); iv adds multiples of 4096B.
    const int lg = gtid & 63;
    const float4* c0 = tab + lg;
    const float4* c1 = tab + lg + 64;
    const float4* c2 = tab + lg + 128;
    const float4* c3 = tab + lg + 192;

#pragma unroll
    for (int k = 0; k < DEPTH; ++k) {
        float4 r;
        r.x = interp1(v[k].x, c0);
        r.y = interp1(v[k].y, c1);
        r.z = interp1(v[k].z, c2);
        r.w = interp1(v[k].w, c3);
        const int id = gtid + k * S;
        if (id < n4) out4[id] = r;
    }
}

extern "C" void kernel_launch(void* const* d_in, const int* in_sizes, int n_in,
                              void* d_out, int out_size)
{
    // metadata order: t, y, W1, b1, W2, b2, args
    const float* y  = (const float*)d_in[1];
    const float* W1 = (const float*)d_in[2];
    const float* b1 = (const float*)d_in[3];
    const float* W2 = (const float*)d_in[4];
    const float* b2 = (const float*)d_in[5];
    float* out = (float*)d_out;

    const int total = in_sizes[1];         // B*L = 4,194,304 (multiple of 4)
    const int n4 = total / 4;

    static int smem_set = 0;
    const int smem_bytes = TAB_F4 * (int)sizeof(float4);   // 65536
    if (!smem_set) {
        cudaFuncSetAttribute(fused_kernel,
                             cudaFuncAttributeMaxDynamicSharedMemorySize,
                             smem_bytes);
        smem_set = 1;
    }

    fused_kernel<<<EV_GRID, EV_BLK, smem_bytes>>>(
        (const float4*)y, (float4*)out, W1, b1, W2, b2, n4);
}